// round 17
// baseline (speedup 1.0000x reference)
#include <cuda_runtime.h>
#include <cuda_bf16.h>
#include <math.h>

#define B_   4
#define N_   4096
#define H_   12
#define DH_  64
#define NB_  266
#define BH_  (B_*H_)           // 48
#define R_   (B_*H_*N_)        // 196608
#define EPS_ 1e-4f

// ---------------- scratch (static device memory; no allocation) ----------------
__device__ float g_v[R_ * DH_];
__device__ float g_kp[R_ * NB_];           // raw dash (never transformed in place)
__device__ float g_qdiag[R_];
__device__ float g_kdiag[R_];
__device__ float g_kmax[BH_];
__device__ float g_ksum_part[4 * BH_ * NB_];
__device__ float g_ctx_part[4 * BH_ * NB_ * DH_];
// bf16 hi/lo split operands
__device__ __nv_bfloat16 g_ahi[16384 * 768];
__device__ __nv_bfloat16 g_alo[16384 * 768];
__device__ __nv_bfloat16 g_whi[2304 * 768];
__device__ __nv_bfloat16 g_wlo[2304 * 768];
__device__ __nv_bfloat16 g_qhi[R_ * DH_];
__device__ __nv_bfloat16 g_qlo[R_ * DH_];
__device__ __nv_bfloat16 g_khi[R_ * DH_];
__device__ __nv_bfloat16 g_klo[R_ * DH_];
__device__ __nv_bfloat16 g_phi[288 * DH_];
__device__ __nv_bfloat16 g_plo[288 * DH_];
// qp as bf16 hi/lo, k-padded to stride 288 (cols >= 266 stay zero)
__device__ __nv_bfloat16 g_qphi[(size_t)R_ * 288];
__device__ __nv_bfloat16 g_qplo[(size_t)R_ * 288];
// B matrix for out GEMM: per bh, [72 rows(n) x 288 k] = [ctx^T | ksum | 0]
__device__ __nv_bfloat16 g_cbhi[BH_ * 72 * 288];
__device__ __nv_bfloat16 g_cblo[BH_ * 72 * 288];

// ---------------- helpers ----------------
static __device__ __forceinline__ unsigned long long pk2(float lo, float hi) {
    unsigned long long r;
    asm("mov.b64 %0, {%1, %2};" : "=l"(r) : "f"(lo), "f"(hi));
    return r;
}
static __device__ __forceinline__ float2 upk2(unsigned long long v) {
    float2 r;
    asm("mov.b64 {%0, %1}, %2;" : "=f"(r.x), "=f"(r.y) : "l"(v));
    return r;
}
static __device__ __forceinline__ void ffma2(unsigned long long& d,
                                             unsigned long long a,
                                             unsigned long long b) {
    asm("fma.rn.f32x2 %0, %1, %2, %0;" : "+l"(d) : "l"(a), "l"(b));
}
static __device__ __forceinline__ void atomicMaxF(float* addr, float v) {
    if (v >= 0.f) atomicMax((int*)addr, __float_as_int(v));
    else          atomicMin((unsigned int*)addr, __float_as_uint(v));
}
static __device__ __forceinline__ unsigned smem_u32(const void* p) {
    unsigned a;
    asm("{ .reg .u64 t; cvta.to.shared.u64 t, %1; cvt.u32.u64 %0, t; }" : "=r"(a) : "l"(p));
    return a;
}

static __device__ __forceinline__ void ldmx4(unsigned& r0, unsigned& r1,
                                             unsigned& r2, unsigned& r3, unsigned a) {
    asm volatile("ldmatrix.sync.aligned.m8n8.x4.shared.b16 {%0,%1,%2,%3}, [%4];"
                 : "=r"(r0), "=r"(r1), "=r"(r2), "=r"(r3) : "r"(a));
}
static __device__ __forceinline__ void ldmx2(unsigned& r0, unsigned& r1, unsigned a) {
    asm volatile("ldmatrix.sync.aligned.m8n8.x2.shared.b16 {%0,%1}, [%2];"
                 : "=r"(r0), "=r"(r1) : "r"(a));
}
static __device__ __forceinline__ void mma16816(float* c, const unsigned* a,
                                                const unsigned* b) {
    asm volatile(
        "mma.sync.aligned.m16n8k16.row.col.f32.bf16.bf16.f32 "
        "{%0,%1,%2,%3}, {%4,%5,%6,%7}, {%8,%9}, {%0,%1,%2,%3};"
        : "+f"(c[0]), "+f"(c[1]), "+f"(c[2]), "+f"(c[3])
        : "r"(a[0]), "r"(a[1]), "r"(a[2]), "r"(a[3]), "r"(b[0]), "r"(b[1]));
}

#define CP16(dst, src) \
    asm volatile("cp.async.ca.shared.global [%0], [%1], 16;" :: "r"(dst), "l"(src))
#define CP_COMMIT() asm volatile("cp.async.commit_group;" ::: "memory")
#define CP_WAIT1()  asm volatile("cp.async.wait_group 1;" ::: "memory")
#define CP_WAIT0()  asm volatile("cp.async.wait_group 0;" ::: "memory")

__global__ void perf_init_kernel() {
    if (threadIdx.x < BH_) g_kmax[threadIdx.x] = -INFINITY;
}

// ---------------- hi/lo bf16 splits ----------------
__global__ __launch_bounds__(256)
void perf_cvt_a(const float* __restrict__ hs) {
    int i = blockIdx.x * blockDim.x + threadIdx.x;      // float4 index
    const int T4 = 16384 * 768 / 4;
    if (i >= T4) return;
    float4 v = ((const float4*)hs)[i];
    __nv_bfloat16 hx = __float2bfloat16_rn(v.x), hy = __float2bfloat16_rn(v.y);
    __nv_bfloat16 hz = __float2bfloat16_rn(v.z), hw = __float2bfloat16_rn(v.w);
    __nv_bfloat162* ph = (__nv_bfloat162*)(g_ahi + i * 4);
    ph[0] = __nv_bfloat162(hx, hy);
    ph[1] = __nv_bfloat162(hz, hw);
    __nv_bfloat162* pl = (__nv_bfloat162*)(g_alo + i * 4);
    pl[0] = __nv_bfloat162(__float2bfloat16_rn(v.x - __bfloat162float(hx)),
                           __float2bfloat16_rn(v.y - __bfloat162float(hy)));
    pl[1] = __nv_bfloat162(__float2bfloat16_rn(v.z - __bfloat162float(hz)),
                           __float2bfloat16_rn(v.w - __bfloat162float(hw)));
}

__global__ __launch_bounds__(256)
void perf_cvt_w(const float* __restrict__ Wq, const float* __restrict__ Wk,
                const float* __restrict__ Wv) {
    int i = blockIdx.x * blockDim.x + threadIdx.x;      // float4 index
    const int T4 = 2304 * 768 / 4;
    if (i >= T4) return;
    int e = i * 4;
    int row = e / 768, col = e - row * 768;
    int z = row / 768;
    const float* W = (z == 0) ? Wq : (z == 1) ? Wk : Wv;
    float4 v = *(const float4*)(W + (size_t)(row - z * 768) * 768 + col);
    __nv_bfloat16 hx = __float2bfloat16_rn(v.x), hy = __float2bfloat16_rn(v.y);
    __nv_bfloat16 hz = __float2bfloat16_rn(v.z), hw = __float2bfloat16_rn(v.w);
    __nv_bfloat162* ph = (__nv_bfloat162*)(g_whi + e);
    ph[0] = __nv_bfloat162(hx, hy);
    ph[1] = __nv_bfloat162(hz, hw);
    __nv_bfloat162* pl = (__nv_bfloat162*)(g_wlo + e);
    pl[0] = __nv_bfloat162(__float2bfloat16_rn(v.x - __bfloat162float(hx)),
                           __float2bfloat16_rn(v.y - __bfloat162float(hy)));
    pl[1] = __nv_bfloat162(__float2bfloat16_rn(v.z - __bfloat162float(hz)),
                           __float2bfloat16_rn(v.w - __bfloat162float(hw)));
}

__global__ __launch_bounds__(256)
void perf_cvt_p(const float* __restrict__ proj) {
    int i = blockIdx.x * blockDim.x + threadIdx.x;      // float4 index
    const int T4 = 288 * 64 / 4;
    if (i >= T4) return;
    int e = i * 4;
    int row = e >> 6;
    float4 v = make_float4(0.f, 0.f, 0.f, 0.f);
    if (row < NB_) v = *(const float4*)(proj + e);
    __nv_bfloat16 hx = __float2bfloat16_rn(v.x), hy = __float2bfloat16_rn(v.y);
    __nv_bfloat16 hz = __float2bfloat16_rn(v.z), hw = __float2bfloat16_rn(v.w);
    __nv_bfloat162* ph = (__nv_bfloat162*)(g_phi + e);
    ph[0] = __nv_bfloat162(hx, hy);
    ph[1] = __nv_bfloat162(hz, hw);
    __nv_bfloat162* pl = (__nv_bfloat162*)(g_plo + e);
    pl[0] = __nv_bfloat162(__float2bfloat16_rn(v.x - __bfloat162float(hx)),
                           __float2bfloat16_rn(v.y - __bfloat162float(hy)));
    pl[1] = __nv_bfloat162(__float2bfloat16_rn(v.z - __bfloat162float(hz)),
                           __float2bfloat16_rn(v.w - __bfloat162float(hw)));
}

// ---------------- QKV GEMM on HMMA: block 128x128, 4 warps 64x64, cp.async x2 --
#define QROW 80
#define S_AH 0
#define S_AL (128 * QROW)
#define S_BH (2 * 128 * QROW)
#define S_BL (3 * 128 * QROW)
#define SSTAGE (4 * 128 * QROW)              // 40960 bytes
#define QKV_SMEM (2 * SSTAGE + 128 * 4)

__global__ __launch_bounds__(128, 2)
void perf_qkv_mma(const float* __restrict__ bq, const float* __restrict__ bk,
                  const float* __restrict__ bv) {
    extern __shared__ __align__(16) unsigned char smq[];
    float* bias_s = (float*)(smq + 2 * SSTAGE);
    unsigned sb = smem_u32(smq);

    int tid = threadIdx.x, wid = tid >> 5, lane = tid & 31;
    int warp_m = wid & 1, warp_n = wid >> 1;
    int m0 = blockIdx.x * 128;
    int n0 = blockIdx.y * 128;
    int z = blockIdx.y / 6;
    int o_base = (blockIdx.y - z * 6) * 128;
    const float* bias = (z == 0) ? bq : (z == 1) ? bk : bv;
    bias_s[tid] = bias[o_base + tid];

    float acc[4][8][4];
#pragma unroll
    for (int mt = 0; mt < 4; mt++)
#pragma unroll
        for (int nt = 0; nt < 8; nt++)
#pragma unroll
            for (int e = 0; e < 4; e++) acc[mt][nt][e] = 0.f;

    int rA = tid >> 2, segA = tid & 3;

    {
        int k0 = 0;
        unsigned st = sb;
#pragma unroll
        for (int i = 0; i < 4; i++) {
            int r = rA + i * 32;
            size_t go = (size_t)(m0 + r) * 768 + k0 + segA * 8;
            unsigned so = (unsigned)(r * QROW + segA * 16);
            CP16(st + S_AH + so, g_ahi + go);
            CP16(st + S_AL + so, g_alo + go);
            size_t gb = (size_t)(n0 + r) * 768 + k0 + segA * 8;
            CP16(st + S_BH + so, g_whi + gb);
            CP16(st + S_BL + so, g_wlo + gb);
        }
        CP_COMMIT();
    }

    for (int ch = 0; ch < 24; ch++) {
        unsigned st = sb + (unsigned)((ch & 1) * SSTAGE);
        if (ch < 23) {
            int k0 = (ch + 1) * 32;
            unsigned st2 = sb + (unsigned)(((ch + 1) & 1) * SSTAGE);
#pragma unroll
            for (int i = 0; i < 4; i++) {
                int r = rA + i * 32;
                size_t go = (size_t)(m0 + r) * 768 + k0 + segA * 8;
                unsigned so = (unsigned)(r * QROW + segA * 16);
                CP16(st2 + S_AH + so, g_ahi + go);
                CP16(st2 + S_AL + so, g_alo + go);
                size_t gb = (size_t)(n0 + r) * 768 + k0 + segA * 8;
                CP16(st2 + S_BH + so, g_whi + gb);
                CP16(st2 + S_BL + so, g_wlo + gb);
            }
            CP_COMMIT();
            CP_WAIT1();
        } else {
            CP_WAIT0();
        }
        __syncthreads();

#pragma unroll
        for (int ks = 0; ks < 2; ks++) {
            unsigned ah[4][4], al[4][4];
#pragma unroll
            for (int mt = 0; mt < 4; mt++) {
                unsigned ra = (unsigned)((warp_m * 64 + mt * 16 + (lane & 15)) * QROW +
                                         ks * 32 + (lane >> 4) * 16);
                ldmx4(ah[mt][0], ah[mt][1], ah[mt][2], ah[mt][3], st + S_AH + ra);
                ldmx4(al[mt][0], al[mt][1], al[mt][2], al[mt][3], st + S_AL + ra);
            }
#pragma unroll
            for (int nt = 0; nt < 8; nt++) {
                unsigned rb = (unsigned)((warp_n * 64 + nt * 8 + (lane & 7)) * QROW +
                                         ks * 32 + ((lane >> 3) & 1) * 16);
                unsigned bh[2], bl[2];
                ldmx2(bh[0], bh[1], st + S_BH + rb);
                ldmx2(bl[0], bl[1], st + S_BL + rb);
#pragma unroll
                for (int mt = 0; mt < 4; mt++) {
                    mma16816(acc[mt][nt], ah[mt], bh);
                    mma16816(acc[mt][nt], ah[mt], bl);
                    mma16816(acc[mt][nt], al[mt], bh);
                }
            }
        }
        __syncthreads();
    }

    // epilogue: add bias; q/k -> bf16 hi/lo + diag, v -> fp32
#pragma unroll
    for (int mt = 0; mt < 4; mt++) {
        float dsum[2] = {0.f, 0.f};
#pragma unroll
        for (int nt = 0; nt < 8; nt++) {
            int cb = warp_n * 64 + nt * 8 + (lane & 3) * 2;
            int oc = o_base + cb;
            int h = oc >> 6, d = oc & 63;
            float bx = bias_s[cb], by = bias_s[cb + 1];
#pragma unroll
            for (int hh = 0; hh < 2; hh++) {
                int gi = m0 + warp_m * 64 + mt * 16 + (lane >> 2) + hh * 8;
                int bbi = gi >> 12, nn = gi & (N_ - 1);
                size_t idx = ((size_t)(bbi * H_ + h) * N_ + nn) * DH_ + d;
                float vx = acc[mt][nt][hh * 2 + 0] + bx;
                float vy = acc[mt][nt][hh * 2 + 1] + by;
                if (z == 2) {
                    *(float2*)(g_v + idx) = make_float2(vx, vy);
                } else {
                    dsum[hh] += vx * vx + vy * vy;
                    __nv_bfloat16* dh = z ? g_khi : g_qhi;
                    __nv_bfloat16* dl = z ? g_klo : g_qlo;
                    __nv_bfloat16 hx = __float2bfloat16_rn(vx);
                    __nv_bfloat16 hy = __float2bfloat16_rn(vy);
                    *(__nv_bfloat162*)(dh + idx) = __nv_bfloat162(hx, hy);
                    *(__nv_bfloat162*)(dl + idx) = __nv_bfloat162(
                        __float2bfloat16_rn(vx - __bfloat162float(hx)),
                        __float2bfloat16_rn(vy - __bfloat162float(hy)));
                }
            }
        }
        if (z < 2) {
            float* dgout = z ? g_kdiag : g_qdiag;
            int h = (o_base + warp_n * 64) >> 6;
#pragma unroll
            for (int hh = 0; hh < 2; hh++) {
                float s = dsum[hh];
                s += __shfl_xor_sync(0xffffffffu, s, 1);
                s += __shfl_xor_sync(0xffffffffu, s, 2);
                if ((lane & 3) == 0) {
                    int gi = m0 + warp_m * 64 + mt * 16 + (lane >> 2) + hh * 8;
                    int bbi = gi >> 12, nn = gi & (N_ - 1);
                    dgout[(size_t)(bbi * H_ + h) * N_ + nn] = 0.0625f * s;
                }
            }
        }
    }
}

// ---------------- FAVOR+ feature map on HMMA --------------------------------
#define FROW 144
#define FS_QH 0
#define FS_QL (128 * FROW)
#define FS_PH (2 * 128 * FROW)
#define FS_PL (FS_PH + 288 * FROW)
#define FS_DIAG (FS_PL + 288 * FROW)          // 119808
#define FS_RMAX (FS_DIAG + 512)
#define FEAT_SMEM (FS_RMAX + 512)

__global__ __launch_bounds__(256)
void perf_feat_mma() {
    extern __shared__ __align__(16) unsigned char smf[];
    float* diag_s = (float*)(smf + FS_DIAG);
    float* rmax_s = (float*)(smf + FS_RMAX);
    unsigned sb = smem_u32(smf);

    int tid = threadIdx.x, wid = tid >> 5, lane = tid & 31;
    int warp_m = wid & 1, warp_n = wid >> 1;
    int which = blockIdx.y;
    int row0 = blockIdx.x * 128;
    const __nv_bfloat16* srcH = which ? g_khi : g_qhi;
    const __nv_bfloat16* srcL = which ? g_klo : g_qlo;

    if (tid < 128) {
        rmax_s[tid] = -INFINITY;
        diag_s[tid] = which ? g_kdiag[row0 + tid] : g_qdiag[row0 + tid];
    }

    for (int i = tid; i < 128 * 8; i += 256) {
        int r = i >> 3, c = i & 7;
        *(uint4*)(smf + FS_QH + r * FROW + c * 16) =
            *(const uint4*)(srcH + (size_t)(row0 + r) * 64 + c * 8);
        *(uint4*)(smf + FS_QL + r * FROW + c * 16) =
            *(const uint4*)(srcL + (size_t)(row0 + r) * 64 + c * 8);
    }
    for (int i = tid; i < 288 * 8; i += 256) {
        int r = i >> 3, c = i & 7;
        *(uint4*)(smf + FS_PH + r * FROW + c * 16) = *(const uint4*)(g_phi + r * 64 + c * 8);
        *(uint4*)(smf + FS_PL + r * FROW + c * 16) = *(const uint4*)(g_plo + r * 64 + c * 8);
    }
    __syncthreads();

    float acc[4][9][4];
#pragma unroll
    for (int mt = 0; mt < 4; mt++)
#pragma unroll
        for (int nt = 0; nt < 9; nt++)
#pragma unroll
            for (int e = 0; e < 4; e++) acc[mt][nt][e] = 0.f;

#pragma unroll
    for (int ks = 0; ks < 4; ks++) {
        unsigned ah[4][4], al[4][4];
#pragma unroll
        for (int mt = 0; mt < 4; mt++) {
            unsigned ra = (unsigned)((warp_m * 64 + mt * 16 + (lane & 15)) * FROW +
                                     ks * 32 + (lane >> 4) * 16);
            ldmx4(ah[mt][0], ah[mt][1], ah[mt][2], ah[mt][3], sb + FS_QH + ra);
            ldmx4(al[mt][0], al[mt][1], al[mt][2], al[mt][3], sb + FS_QL + ra);
        }
#pragma unroll
        for (int nt = 0; nt < 9; nt++) {
            unsigned rb = (unsigned)((warp_n * 72 + nt * 8 + (lane & 7)) * FROW +
                                     ks * 32 + ((lane >> 3) & 1) * 16);
            unsigned bh[2], bl[2];
            ldmx2(bh[0], bh[1], sb + FS_PH + rb);
            ldmx2(bl[0], bl[1], sb + FS_PL + rb);
#pragma unroll
            for (int mt = 0; mt < 4; mt++) {
                mma16816(acc[mt][nt], ah[mt], bh);
                mma16816(acc[mt][nt], ah[mt], bl);
                mma16816(acc[mt][nt], al[mt], bh);
            }
        }
    }

    const float DN = 0.3535533905932738f;      // 64^-0.25
    const float RATIO = 0.06131393394849658f;  // 266^-0.5

    if (which == 0) {
#pragma unroll
        for (int mt = 0; mt < 4; mt++) {
#pragma unroll
            for (int hh = 0; hh < 2; hh++) {
                float m = -INFINITY;
#pragma unroll
                for (int nt = 0; nt < 9; nt++) {
                    int col = warp_n * 72 + nt * 8 + (lane & 3) * 2;
                    if (col < NB_)
                        m = fmaxf(m, fmaxf(acc[mt][nt][hh * 2], acc[mt][nt][hh * 2 + 1]));
                }
                m = fmaxf(m, __shfl_xor_sync(0xffffffffu, m, 1));
                m = fmaxf(m, __shfl_xor_sync(0xffffffffu, m, 2));
                if ((lane & 3) == 0)
                    atomicMaxF(&rmax_s[warp_m * 64 + mt * 16 + (lane >> 2) + hh * 8], m * DN);
            }
        }
        __syncthreads();
#pragma unroll
        for (int mt = 0; mt < 4; mt++) {
#pragma unroll
            for (int hh = 0; hh < 2; hh++) {
                int rl = warp_m * 64 + mt * 16 + (lane >> 2) + hh * 8;
                float c = diag_s[rl] + rmax_s[rl];
                size_t rbase = (size_t)(row0 + rl) * 288;
#pragma unroll
                for (int nt = 0; nt < 9; nt++) {
                    int col = warp_n * 72 + nt * 8 + (lane & 3) * 2;
                    if (col < NB_) {
                        float ox = RATIO * (expf(acc[mt][nt][hh * 2] * DN - c) + EPS_);
                        float oy = RATIO * (expf(acc[mt][nt][hh * 2 + 1] * DN - c) + EPS_);
                        __nv_bfloat16 hx = __float2bfloat16_rn(ox);
                        __nv_bfloat16 hy = __float2bfloat16_rn(oy);
                        *(__nv_bfloat162*)(g_qphi + rbase + col) = __nv_bfloat162(hx, hy);
                        *(__nv_bfloat162*)(g_qplo + rbase + col) = __nv_bfloat162(
                            __float2bfloat16_rn(ox - __bfloat162float(hx)),
                            __float2bfloat16_rn(oy - __bfloat162float(hy)));
                    }
                }
            }
        }
    } else {
        // key path: store raw dash*DN; block max -> g_kmax[bh]
        float m = -INFINITY;
#pragma unroll
        for (int mt = 0; mt < 4; mt++) {
#pragma unroll
            for (int hh = 0; hh < 2; hh++) {
                int rl = warp_m * 64 + mt * 16 + (lane >> 2) + hh * 8;
                float* dr = g_kp + (size_t)(row0 + rl) * NB_;
#pragma unroll
                for (int nt = 0; nt < 9; nt++) {
                    int col = warp_n * 72 + nt * 8 + (lane & 3) * 2;
                    if (col < NB_) {
                        float x = acc[mt][nt][hh * 2] * DN;
                        float y = acc[mt][nt][hh * 2 + 1] * DN;
                        m = fmaxf(m, fmaxf(x, y));
                        *(float2*)(dr + col) = make_float2(x, y);
                    }
                }
            }
        }
#pragma unroll
        for (int o = 16; o; o >>= 1) m = fmaxf(m, __shfl_xor_sync(0xffffffffu, m, o));
        if (lane == 0) atomicMaxF(&rmax_s[0], m);
        __syncthreads();
        if (tid == 0) atomicMaxF(&g_kmax[row0 >> 12], rmax_s[0]);
    }
}

// ---------------- ctx = kp^T v + fused exp + fused partial ksum ---------------
__global__ __launch_bounds__(256)
void perf_ctx_kernel() {
    const float RATIO = 0.06131393394849658f;
    __shared__ float kt[16][68];
    __shared__ float vt[16][68];
    __shared__ float red[8][64];
    int jt = blockIdx.x, kspl = blockIdx.y, bh = blockIdx.z;
    int j0 = jt * 64, n0 = kspl * 1024;
    int tid = threadIdx.x, tx = tid & 15, ty = tid >> 4;
    const float* kbase = g_kp + (size_t)bh * N_ * NB_;
    const float* vbase = g_v + (size_t)bh * N_ * DH_;
    const float* dgbase = g_kdiag + bh * N_;
    float kmaxv = g_kmax[bh];

    unsigned long long acc2[4][2];
#pragma unroll
    for (int a = 0; a < 4; a++) { acc2[a][0] = 0ull; acc2[a][1] = 0ull; }
    float ks0 = 0.f, ks1 = 0.f;

    for (int nn = 0; nn < 1024; nn += 16) {
#pragma unroll
        for (int i = 0; i < 2; i++) {
            int id = i * 256 + tid;
            int r = id >> 5, c2 = id & 31;
            int j = j0 + c2 * 2;
            float2 o = make_float2(0.f, 0.f);
            if (j + 1 < NB_) {
                int row = n0 + nn + r;
                float c = dgbase[row] + kmaxv;
                float2 v = *(const float2*)(kbase + (size_t)row * NB_ + j);
                o.x = RATIO * (expf(v.x - c) + EPS_);
                o.y = RATIO * (expf(v.y - c) + EPS_);
            }
            ks0 += o.x;
            ks1 += o.y;
            kt[r][c2 * 2] = o.x;
            kt[r][c2 * 2 + 1] = o.y;
        }
        {
            int r = tid >> 4, c4 = tid & 15;
            float4 v = *(const float4*)(vbase + (size_t)(n0 + nn + r) * DH_ + c4 * 4);
            *(float4*)(&vt[r][c4 * 4]) = v;
        }
        __syncthreads();
#pragma unroll
        for (int k = 0; k < 16; k++) {
            float4 a = *(float4*)(&kt[k][ty * 4]);
            float4 b = *(float4*)(&vt[k][tx * 4]);
            unsigned long long b01 = pk2(b.x, b.y);
            unsigned long long b23 = pk2(b.z, b.w);
            float av[4] = {a.x, a.y, a.z, a.w};
#pragma unroll
            for (int i = 0; i < 4; i++) {
                unsigned long long ad = pk2(av[i], av[i]);
                ffma2(acc2[i][0], ad, b01);
                ffma2(acc2[i][1], ad, b23);
            }
        }
        __syncthreads();
    }

    {
        int rg = tid >> 5, c2 = tid & 31;
        red[rg][c2 * 2] = ks0;
        red[rg][c2 * 2 + 1] = ks1;
    }
    __syncthreads();
    if (tid < 64) {
        float s = 0.f;
#pragma unroll
        for (int g = 0; g < 8; g++) s += red[g][tid];
        int j = j0 + tid;
        if (j < NB_) g_ksum_part[(bh * 4 + kspl) * NB_ + j] = s;
    }

    float* obase = g_ctx_part + (size_t)(kspl * BH_ + bh) * NB_ * DH_;
#pragma unroll
    for (int jj = 0; jj < 4; jj++) {
        int j = j0 + ty * 4 + jj;
        if (j < NB_) {
            float2 p0 = upk2(acc2[jj][0]);
            float2 p1 = upk2(acc2[jj][1]);
            *(float4*)(&obase[(size_t)j * DH_ + tx * 4]) =
                make_float4(p0.x, p0.y, p1.x, p1.y);
        }
    }
}

// ---------------- ctx/ksum -> transposed bf16 hi/lo B matrix [72 x 288] -------
__global__ __launch_bounds__(256)
void perf_ctxbf() {
    int bh = blockIdx.y;
    int idx = blockIdx.x * 256 + threadIdx.x;
    const int TOT = 65 * NB_;               // d in [0,65), j in [0,266)
    if (idx >= TOT) return;
    int d = idx / NB_, j = idx - d * NB_;
    const int T = BH_ * NB_ * DH_;
    float val;
    if (d < 64) {
        size_t o = (size_t)bh * NB_ * DH_ + (size_t)j * DH_ + d;
        val = g_ctx_part[o] + g_ctx_part[o + T] + g_ctx_part[o + 2 * (size_t)T] +
              g_ctx_part[o + 3 * (size_t)T];
    } else {
        int o = bh * 4 * NB_ + j;
        val = g_ksum_part[o] + g_ksum_part[o + NB_] + g_ksum_part[o + 2 * NB_] +
              g_ksum_part[o + 3 * NB_];
    }
    __nv_bfloat16 hi = __float2bfloat16_rn(val);
    size_t oo = ((size_t)bh * 72 + d) * 288 + j;
    g_cbhi[oo] = hi;
    g_cblo[oo] = __float2bfloat16_rn(val - __bfloat162float(hi));
}

// ---------------- out GEMM on HMMA: qp[128x272] @ [ctx|ksum]^T[72x272] --------
#define OROW 560
#define O_AH 0
#define O_AL (128 * OROW)
#define O_BH (2 * 128 * OROW)
#define O_BL (O_BH + 72 * OROW)
#define OUT_SMEM (O_BL + 72 * OROW)          // 224000 bytes

__global__ __launch_bounds__(256, 1)
void perf_out_mma(float* __restrict__ out) {
    extern __shared__ __align__(16) unsigned char smo[];
    unsigned sb = smem_u32(smo);
    int tid = threadIdx.x, wid = tid >> 5, lane = tid & 31;
    int row0 = blockIdx.x * 128;
    int bh = row0 >> 12;

    // A: 128 rows x 272 bf16 (hi/lo), row pitch 560 B
    for (int i = tid; i < 128 * 34; i += 256) {
        int r = i / 34, c = i - r * 34;
        *(uint4*)(smo + O_AH + r * OROW + c * 16) =
            *(const uint4*)(g_qphi + (size_t)(row0 + r) * 288 + c * 8);
        *(uint4*)(smo + O_AL + r * OROW + c * 16) =
            *(const uint4*)(g_qplo + (size_t)(row0 + r) * 288 + c * 8);
    }
    // B: 72 rows x 272 bf16 (hi/lo)
    for (int i = tid; i < 72 * 34; i += 256) {
        int r = i / 34, c = i - r * 34;
        *(uint4*)(smo + O_BH + r * OROW + c * 16) =
            *(const uint4*)(g_cbhi + ((size_t)bh * 72 + r) * 288 + c * 8);
        *(uint4*)(smo + O_BL + r * OROW + c * 16) =
            *(const uint4*)(g_cblo + ((size_t)bh * 72 + r) * 288 + c * 8);
    }
    __syncthreads();

    float acc[9][4];
#pragma unroll
    for (int nt = 0; nt < 9; nt++)
#pragma unroll
        for (int e = 0; e < 4; e++) acc[nt][e] = 0.f;

#pragma unroll 1
    for (int ks = 0; ks < 17; ks++) {
        unsigned ah[4], al[4];
        unsigned ra = (unsigned)((wid * 16 + (lane & 15)) * OROW + ks * 32 + (lane >> 4) * 16);
        ldmx4(ah[0], ah[1], ah[2], ah[3], sb + O_AH + ra);
        ldmx4(al[0], al[1], al[2], al[3], sb + O_AL + ra);
#pragma unroll
        for (int nt = 0; nt < 9; nt++) {
            unsigned rb = (unsigned)((nt * 8 + (lane & 7)) * OROW + ks * 32 +
                                     ((lane >> 3) & 1) * 16);
            unsigned bhf[2], blf[2];
            ldmx2(bhf[0], bhf[1], sb + O_BH + rb);
            ldmx2(blf[0], blf[1], sb + O_BL + rb);
            mma16816(acc[nt], ah, bhf);
            mma16816(acc[nt], ah, blf);
            mma16816(acc[nt], al, bhf);
        }
    }

    int bb = bh / H_, h = bh - bb * H_;
#pragma unroll
    for (int hh = 0; hh < 2; hh++) {
        // denominator = column 64 -> held by (lane&3)==0 at nt=8
        float denom = __shfl_sync(0xffffffffu, acc[8][hh * 2], lane & 28);
        float dinv = 1.0f / denom;
        int row = row0 + wid * 16 + (lane >> 2) + hh * 8;
        int n = row & (N_ - 1);
        float* op = out + ((size_t)(bb * N_ + n)) * 768 + h * 64;
#pragma unroll
        for (int nt = 0; nt < 8; nt++) {
            int d = nt * 8 + (lane & 3) * 2;
            *(float2*)(op + d) = make_float2(acc[nt][hh * 2] * dinv,
                                             acc[nt][hh * 2 + 1] * dinv);
        }
    }
}

// ---------------- launch ----------------
extern "C" void kernel_launch(void* const* d_in, const int* in_sizes, int n_in,
                              void* d_out, int out_size) {
    (void)in_sizes; (void)n_in; (void)out_size;
    const float* hs   = (const float*)d_in[0];
    const float* Wq   = (const float*)d_in[1];
    const float* bq   = (const float*)d_in[2];
    const float* Wk   = (const float*)d_in[3];
    const float* bk   = (const float*)d_in[4];
    const float* Wv   = (const float*)d_in[5];
    const float* bv   = (const float*)d_in[6];
    const float* proj = (const float*)d_in[7];
    float* out = (float*)d_out;

    cudaFuncSetAttribute(perf_qkv_mma,  cudaFuncAttributeMaxDynamicSharedMemorySize, QKV_SMEM);
    cudaFuncSetAttribute(perf_feat_mma, cudaFuncAttributeMaxDynamicSharedMemorySize, FEAT_SMEM);
    cudaFuncSetAttribute(perf_out_mma,  cudaFuncAttributeMaxDynamicSharedMemorySize, OUT_SMEM);

    perf_init_kernel<<<1, 64>>>();
    perf_cvt_a<<<(16384 * 768 / 4 + 255) / 256, 256>>>(hs);
    perf_cvt_w<<<(2304 * 768 / 4 + 255) / 256, 256>>>(Wq, Wk, Wv);
    perf_cvt_p<<<(288 * 64 / 4 + 255) / 256, 256>>>(proj);
    perf_qkv_mma<<<dim3(128, 18), 128, QKV_SMEM>>>(bq, bk, bv);
    perf_feat_mma<<<dim3(R_ / 128, 2), 256, FEAT_SMEM>>>();
    perf_ctx_kernel<<<dim3(5, 4, BH_), 256>>>();
    perf_ctxbf<<<dim3((65 * NB_ + 255) / 256, BH_), 256>>>();
    perf_out_mma<<<R_ / 128, 256, OUT_SMEM>>>(out);
}